// round 1
// baseline (speedup 1.0000x reference)
#include <cuda_runtime.h>
#include <cuda_bf16.h>
#include <cstdint>

// Problem constants
#define BB   16
#define TT   32
#define HH   512
#define PP   1024          // 32*32 spatial positions
#define OO   2048          // 4*H gate channels
#define KK   513           // 1 + H input channels to the 1x1 conv

// GEMM tiling
#define TILE 128
#define KT   8

// Persistent state / scratch (allocation-free rule: __device__ globals)
__device__ float g_h[(size_t)BB * HH * PP];          // 33.5 MB
__device__ float g_c[(size_t)BB * HH * PP];          // 33.5 MB
__device__ float g_gates[(size_t)BB * OO * PP];      // 134 MB

// ---------------------------------------------------------------------------
// Zero h and c state at the start of every launch (determinism)
// ---------------------------------------------------------------------------
__global__ void zero_state_kernel() {
    size_t i = (size_t)blockIdx.x * blockDim.x + threadIdx.x;
    if (i < (size_t)BB * HH * PP) {
        g_h[i] = 0.0f;
        g_c[i] = 0.0f;
    }
}

// ---------------------------------------------------------------------------
// gates[b, o, p] = sum_c h[b, c, p] * W[o, 1+c]  +  W[o,0]*x[b,t,p] + bias[o]
// Per-batch GEMM: M=2048 (o), N=1024 (p), K=512 (c).
// 128x128 tile, KT=8, 256 threads, 8x8 per thread (4+4 split for LDS.128).
// ---------------------------------------------------------------------------
__global__ __launch_bounds__(256) void gemm_gates_kernel(
    const float* __restrict__ W,      // [2048][513]
    const float* __restrict__ bconv,  // [2048]
    const float* __restrict__ x,      // [B][T][1024]
    int t)
{
    __shared__ float As[KT][TILE];    // As[kk][row(o)]
    __shared__ float Bs[KT][TILE];    // Bs[kk][col(p)]

    const int b   = blockIdx.z;
    const int o0  = blockIdx.y * TILE;
    const int p0  = blockIdx.x * TILE;
    const int tid = threadIdx.x;

    const float* __restrict__ hb = g_h + (size_t)b * HH * PP;

    const int ty = tid >> 4;   // 0..15
    const int tx = tid & 15;   // 0..15

    float acc[8][8];
#pragma unroll
    for (int i = 0; i < 8; i++)
#pragma unroll
        for (int j = 0; j < 8; j++) acc[i][j] = 0.0f;

    // Per-thread fixed load coordinates
    const int a_row = tid & 127;         // o row within tile
    const int a_kk0 = tid >> 7;          // 0 or 1
    const int b_pp  = tid & 127;
    const int b_kk0 = tid >> 7;

    for (int k0 = 0; k0 < HH; k0 += KT) {
        // Load A tile: W[o0+row][1 + k0 + kk]   (sector-local per thread)
#pragma unroll
        for (int i = 0; i < 4; i++) {
            int kk = a_kk0 + 2 * i;
            As[kk][a_row] = W[(size_t)(o0 + a_row) * KK + 1 + k0 + kk];
        }
        // Load B tile: h[b][k0+kk][p0+pp]  (coalesced)
#pragma unroll
        for (int i = 0; i < 4; i++) {
            int kk = b_kk0 + 2 * i;
            Bs[kk][b_pp] = hb[(size_t)(k0 + kk) * PP + p0 + b_pp];
        }
        __syncthreads();

#pragma unroll
        for (int kk = 0; kk < KT; kk++) {
            float4 a0 = *(const float4*)&As[kk][ty * 4];
            float4 a1 = *(const float4*)&As[kk][64 + ty * 4];
            float4 b0 = *(const float4*)&Bs[kk][tx * 4];
            float4 b1 = *(const float4*)&Bs[kk][64 + tx * 4];
            float ar[8] = {a0.x, a0.y, a0.z, a0.w, a1.x, a1.y, a1.z, a1.w};
            float br[8] = {b0.x, b0.y, b0.z, b0.w, b1.x, b1.y, b1.z, b1.w};
#pragma unroll
            for (int i = 0; i < 8; i++)
#pragma unroll
                for (int j = 0; j < 8; j++)
                    acc[i][j] += ar[i] * br[j];
        }
        __syncthreads();
    }

    // Epilogue: + W[o,0]*x + bias, write gates
    const float* __restrict__ xb = x + ((size_t)b * TT + t) * PP + p0;
    float xr[8];
#pragma unroll
    for (int j = 0; j < 8; j++) {
        int p = (j < 4) ? (tx * 4 + j) : (64 + tx * 4 + j - 4);
        xr[j] = xb[p];
    }

    float* __restrict__ gb = g_gates + (size_t)b * OO * PP;
#pragma unroll
    for (int i = 0; i < 8; i++) {
        int o = o0 + ((i < 4) ? (ty * 4 + i) : (64 + ty * 4 + i - 4));
        float w0   = W[(size_t)o * KK];
        float bias = bconv[o];
        float* __restrict__ gout = gb + (size_t)o * PP + p0;
#pragma unroll
        for (int j = 0; j < 8; j++) {
            int p = (j < 4) ? (tx * 4 + j) : (64 + tx * 4 + j - 4);
            gout[p] = acc[i][j] + w0 * xr[j] + bias;
        }
    }
}

// ---------------------------------------------------------------------------
// LSTM pointwise update (reference variant):
//   c = sigmoid(f)*c + sigmoid(i) + tanh(g);  h = sigmoid(o) + tanh(c)
// ---------------------------------------------------------------------------
__device__ __forceinline__ float sigf(float v) {
    return 1.0f / (1.0f + __expf(-v));
}

__global__ __launch_bounds__(256) void lstm_pointwise_kernel() {
    size_t idx = (size_t)blockIdx.x * 256 + threadIdx.x;   // over B*H*P = 2^23
    if (idx >= (size_t)BB * HH * PP) return;
    int b = (int)(idx >> 19);                 // H*P = 2^19
    int r = (int)(idx & ((1u << 19) - 1));    // ch*1024 + p
    const float* __restrict__ gb = g_gates + ((size_t)b << 21);  // O*P = 2^21
    float gi = gb[r];
    float gf = gb[r + (512 << 10)];
    float go = gb[r + (1024 << 10)];
    float gg = gb[r + (1536 << 10)];
    float c  = g_c[idx];
    c = sigf(gf) * c + sigf(gi) + tanhf(gg);
    g_c[idx] = c;
    g_h[idx] = sigf(go) + tanhf(c);
}

// ---------------------------------------------------------------------------
// Post conv: y[b,t,py,px] = b_post + sum_{c,ky,kx} h[b,c,py+ky-1,px+kx-1]*Wp[c,ky,kx]
// One block per (b, py); 256 threads = 32 px * 8 channel groups.
// ---------------------------------------------------------------------------
__global__ __launch_bounds__(256) void post_conv_kernel(
    const float* __restrict__ Wp,     // [512][3][3]
    const float* __restrict__ bpost,  // [1]
    float* __restrict__ out,          // [B][T][32][32]
    int t)
{
    const int b  = blockIdx.y;
    const int py = blockIdx.x;
    const int px = threadIdx.x & 31;
    const int cg = threadIdx.x >> 5;   // 0..7

    const float* __restrict__ hb = g_h + (size_t)b * HH * PP;

    float acc = 0.0f;
    for (int c = cg; c < HH; c += 8) {
        const float* __restrict__ hc = hb + (size_t)c * PP;
        const float* __restrict__ w  = Wp + c * 9;
#pragma unroll
        for (int ky = 0; ky < 3; ky++) {
            int yy = py + ky - 1;
            if (yy < 0 || yy > 31) continue;
            const float* __restrict__ hrow = hc + yy * 32;
#pragma unroll
            for (int kx = 0; kx < 3; kx++) {
                int xx = px + kx - 1;
                if (xx >= 0 && xx <= 31)
                    acc += hrow[xx] * w[ky * 3 + kx];
            }
        }
    }

    __shared__ float red[8][32];
    red[cg][px] = acc;
    __syncthreads();
    if (cg == 0) {
        float s = acc;
#pragma unroll
        for (int g = 1; g < 8; g++) s += red[g][px];
        out[((size_t)b * TT + t) * PP + py * 32 + px] = s + bpost[0];
    }
}

// ---------------------------------------------------------------------------
// Launch: zero state, then 32 sequential steps of (gemm, pointwise, conv)
// ---------------------------------------------------------------------------
extern "C" void kernel_launch(void* const* d_in, const int* in_sizes, int n_in,
                              void* d_out, int out_size)
{
    const float* x      = (const float*)d_in[0];  // [16][32][32][32]
    const float* W_conv = (const float*)d_in[1];  // [2048][513][1][1]
    const float* b_conv = (const float*)d_in[2];  // [2048]
    const float* W_post = (const float*)d_in[3];  // [1][512][3][3]
    const float* b_post = (const float*)d_in[4];  // [1]
    float* out = (float*)d_out;                   // [16][32][32][32]

    {
        size_t n = (size_t)BB * HH * PP;
        int grid = (int)((n + 255) / 256);
        zero_state_kernel<<<grid, 256>>>();
    }

    dim3 ggrid(PP / TILE, OO / TILE, BB);   // (8, 16, 16)
    int pgrid = (int)(((size_t)BB * HH * PP + 255) / 256);
    dim3 cgrid(32, BB);

    for (int t = 0; t < TT; t++) {
        gemm_gates_kernel<<<ggrid, 256>>>(W_conv, b_conv, x, t);
        lstm_pointwise_kernel<<<pgrid, 256>>>();
        post_conv_kernel<<<cgrid, 256>>>(W_post, b_post, out, t);
    }
}